// round 1
// baseline (speedup 1.0000x reference)
#include <cuda_runtime.h>

#define S_LEN 256

__device__ __forceinline__ float ex2f(float v) {
    float y;
    asm("ex2.approx.ftz.f32 %0, %1;" : "=f"(y) : "f"(v));
    return y;
}

__global__ void __launch_bounds__(S_LEN)
pico_transformer_adder_kernel(
    const float* __restrict__ x,
    const float* __restrict__ emb_w,
    const float* __restrict__ emb_b,
    const float* __restrict__ q_w,
    const float* __restrict__ q_b,
    const float* __restrict__ k_w,
    const float* __restrict__ k_b,
    const float* __restrict__ v_w,
    const float* __restrict__ v_b,
    const float* __restrict__ f1_w,
    const float* __restrict__ f1_b,
    const float* __restrict__ f2_w,
    const float* __restrict__ f2_b,
    float* __restrict__ out)
{
    __shared__ __align__(16) float xs[S_LEN];
    __shared__ float smx[8], smn[8], ssum[8];

    const int b    = blockIdx.x;
    const int t    = threadIdx.x;
    const int lane = t & 31;
    const int wid  = t >> 5;

    const float xi = x[b * S_LEN + t];
    xs[t] = xi;

    // ---------- uniform scalar constants: alpha_i = A*x_i + C ----------
    // h[s,:] = x_s*w + bb  (w = emb_w[:,0], bb = emb_b)
    // q_s = x_s*qa + qc ; k_s = x_s*ka + kc
    // scores[i,j] (mod row-const) = x_j * (A x_i + C),
    //   A = (qa.ka)/sqrt(d)=.../2 , C = (qc.ka)/2
    const float w0 = emb_w[0], w1 = emb_w[1], w2 = emb_w[2], w3 = emb_w[3];
    const float e0 = emb_b[0], e1 = emb_b[1], e2 = emb_b[2], e3 = emb_b[3];

    float A = 0.f, C = 0.f;
    #pragma unroll
    for (int e = 0; e < 4; ++e) {
        const float qw0 = q_w[e*4+0], qw1 = q_w[e*4+1], qw2 = q_w[e*4+2], qw3 = q_w[e*4+3];
        const float kw0 = k_w[e*4+0], kw1 = k_w[e*4+1], kw2 = k_w[e*4+2], kw3 = k_w[e*4+3];
        const float qa = qw0*w0 + qw1*w1 + qw2*w2 + qw3*w3;
        const float qc = qw0*e0 + qw1*e1 + qw2*e2 + qw3*e3 + q_b[e];
        const float ka = kw0*w0 + kw1*w1 + kw2*w2 + kw3*w3;
        A = fmaf(qa, ka, A);
        C = fmaf(qc, ka, C);
    }
    A *= 0.5f;   // 1/sqrt(d), d=4
    C *= 0.5f;

    // ---------- block min/max of x (softmax stability) ----------
    float mx = xi, mn = xi;
    #pragma unroll
    for (int o = 16; o; o >>= 1) {
        mx = fmaxf(mx, __shfl_xor_sync(0xffffffffu, mx, o));
        mn = fminf(mn, __shfl_xor_sync(0xffffffffu, mn, o));
    }
    if (lane == 0) { smx[wid] = mx; smn[wid] = mn; }
    __syncthreads();
    mx = smx[0]; mn = smn[0];
    #pragma unroll
    for (int i = 1; i < 8; ++i) { mx = fmaxf(mx, smx[i]); mn = fminf(mn, smn[i]); }

    // ---------- tilted mean m_i = sum_j exp(a x_j) x_j / sum_j exp(a x_j) ----------
    const float LOG2E = 1.4426950408889634f;
    const float alpha = fmaf(A, xi, C);
    const float a2    = alpha * LOG2E;
    const float mrow  = a2 * ((a2 >= 0.f) ? mx : mn);  // max_j a2*x_j

    float s0 = 0.f, s1 = 0.f;
    const float4* x4 = (const float4*)xs;
    #pragma unroll 8
    for (int j = 0; j < S_LEN / 4; ++j) {
        const float4 v = x4[j];
        const float p0 = ex2f(fmaf(a2, v.x, -mrow));
        const float p1 = ex2f(fmaf(a2, v.y, -mrow));
        const float p2 = ex2f(fmaf(a2, v.z, -mrow));
        const float p3 = ex2f(fmaf(a2, v.w, -mrow));
        s0 += (p0 + p1) + (p2 + p3);
        s1 = fmaf(p0, v.x, s1);
        s1 = fmaf(p1, v.y, s1);
        s1 = fmaf(p2, v.z, s1);
        s1 = fmaf(p3, v.w, s1);
    }
    float m = s1 / s0;

    // ---------- block mean of m ----------
    #pragma unroll
    for (int o = 16; o; o >>= 1) m += __shfl_xor_sync(0xffffffffu, m, o);
    if (lane == 0) ssum[wid] = m;
    __syncthreads();

    if (t == 0) {
        float M = 0.f;
        #pragma unroll
        for (int i = 0; i < 8; ++i) M += ssum[i];
        M *= (1.0f / (float)S_LEN);

        // pooled = va*M + vc  (v_s = x_s*va + vc, out_i = va*m_i + vc, mean over i)
        float pooled[4];
        #pragma unroll
        for (int e = 0; e < 4; ++e) {
            const float vw0 = v_w[e*4+0], vw1 = v_w[e*4+1], vw2 = v_w[e*4+2], vw3 = v_w[e*4+3];
            const float va = vw0*w0 + vw1*w1 + vw2*w2 + vw3*w3;
            const float vc = vw0*e0 + vw1*e1 + vw2*e2 + vw3*e3 + v_b[e];
            pooled[e] = fmaf(va, M, vc);
        }

        float y = f2_b[0];
        #pragma unroll
        for (int tt = 0; tt < 8; ++tt) {
            float h = f1_b[tt];
            #pragma unroll
            for (int e = 0; e < 4; ++e) h = fmaf(f1_w[tt*4+e], pooled[e], h);
            h = fmaxf(h, 0.f);
            y = fmaf(f2_w[tt], h, y);
        }
        out[b] = y;
    }
}

extern "C" void kernel_launch(void* const* d_in, const int* in_sizes, int n_in,
                              void* d_out, int out_size) {
    const float* x     = (const float*)d_in[0];
    const float* emb_w = (const float*)d_in[1];
    const float* emb_b = (const float*)d_in[2];
    const float* q_w   = (const float*)d_in[3];
    const float* q_b   = (const float*)d_in[4];
    const float* k_w   = (const float*)d_in[5];
    const float* k_b   = (const float*)d_in[6];
    const float* v_w   = (const float*)d_in[7];
    const float* v_b   = (const float*)d_in[8];
    const float* f1_w  = (const float*)d_in[9];
    const float* f1_b  = (const float*)d_in[10];
    const float* f2_w  = (const float*)d_in[11];
    const float* f2_b  = (const float*)d_in[12];

    const int B = in_sizes[0] / S_LEN;

    pico_transformer_adder_kernel<<<B, S_LEN>>>(
        x, emb_w, emb_b, q_w, q_b, k_w, k_b, v_w, v_b,
        f1_w, f1_b, f2_w, f2_b, (float*)d_out);
}

// round 2
// speedup vs baseline: 1.1007x; 1.1007x over previous
#include <cuda_runtime.h>

#define S_LEN 256
#define GN 32          // interpolation grid nodes
#define SLICES 8       // threads cooperating per node (GN*SLICES == S_LEN)

__device__ __forceinline__ float ex2f(float v) {
    float y;
    asm("ex2.approx.ftz.f32 %0, %1;" : "=f"(y) : "f"(v));
    return y;
}

__global__ void __launch_bounds__(S_LEN)
pico_transformer_adder_kernel(
    const float* __restrict__ x,
    const float* __restrict__ emb_w,
    const float* __restrict__ emb_b,
    const float* __restrict__ q_w,
    const float* __restrict__ q_b,
    const float* __restrict__ k_w,
    const float* __restrict__ k_b,
    const float* __restrict__ v_w,
    const float* __restrict__ v_b,
    const float* __restrict__ f1_w,
    const float* __restrict__ f1_b,
    const float* __restrict__ f2_w,
    const float* __restrict__ f2_b,
    float* __restrict__ out)
{
    __shared__ __align__(16) float xs[S_LEN];
    __shared__ float smx[8], smn[8], ssum[8];
    __shared__ float mArr[GN], dArr[GN];

    const int b    = blockIdx.x;
    const int t    = threadIdx.x;
    const int lane = t & 31;
    const int wid  = t >> 5;

    const float xi = x[b * S_LEN + t];
    xs[t] = xi;

    // ---------- uniform scalar constants: alpha_i = A*x_i + C ----------
    const float w0 = emb_w[0], w1 = emb_w[1], w2 = emb_w[2], w3 = emb_w[3];
    const float e0 = emb_b[0], e1 = emb_b[1], e2 = emb_b[2], e3 = emb_b[3];

    float A = 0.f, C = 0.f;
    #pragma unroll
    for (int e = 0; e < 4; ++e) {
        const float qw0 = q_w[e*4+0], qw1 = q_w[e*4+1], qw2 = q_w[e*4+2], qw3 = q_w[e*4+3];
        const float kw0 = k_w[e*4+0], kw1 = k_w[e*4+1], kw2 = k_w[e*4+2], kw3 = k_w[e*4+3];
        const float qa = qw0*w0 + qw1*w1 + qw2*w2 + qw3*w3;
        const float qc = qw0*e0 + qw1*e1 + qw2*e2 + qw3*e3 + q_b[e];
        const float ka = kw0*w0 + kw1*w1 + kw2*w2 + kw3*w3;
        A = fmaf(qa, ka, A);
        C = fmaf(qc, ka, C);
    }
    A *= 0.5f;   // 1/sqrt(d), d=4
    C *= 0.5f;

    // ---------- block min/max of x ----------
    float mx = xi, mn = xi;
    #pragma unroll
    for (int o = 16; o; o >>= 1) {
        mx = fmaxf(mx, __shfl_xor_sync(0xffffffffu, mx, o));
        mn = fminf(mn, __shfl_xor_sync(0xffffffffu, mn, o));
    }
    if (lane == 0) { smx[wid] = mx; smn[wid] = mn; }
    __syncthreads();                      // also publishes xs[]
    mx = smx[0]; mn = smn[0];
    #pragma unroll
    for (int i = 1; i < 8; ++i) { mx = fmaxf(mx, smx[i]); mn = fminf(mn, smn[i]); }

    // ---------- alpha range and grid ----------
    const float LOG2E = 1.4426950408889634f;
    const float alo = (A >= 0.f) ? fmaf(A, mn, C) : fmaf(A, mx, C);
    const float ahi = (A >= 0.f) ? fmaf(A, mx, C) : fmaf(A, mn, C);
    const float hstep = fmaxf((ahi - alo) * (1.0f / (float)(GN - 1)), 1e-30f);

    // ---------- grid phase: tilted sums at node g over a 32-element slice ----------
    const int g  = t >> 3;      // node 0..31
    const int sl = t & 7;       // slice 0..7 (xor 1,2,4 stays intra-warp)

    const float ag  = fmaf((float)g, hstep, alo);
    const float ag2 = ag * LOG2E;
    const float mg  = fmaxf(ag2 * mx, ag2 * mn);   // max_j ag2*x_j (achieved by data)

    float s0 = 0.f, s1 = 0.f, s2 = 0.f;
    const float4* x4 = (const float4*)(xs + sl * 32);
    #pragma unroll
    for (int j = 0; j < 8; ++j) {
        const float4 v = x4[j];
        float p, px;
        p  = ex2f(fmaf(ag2, v.x, -mg)); px = p * v.x; s0 += p; s1 += px; s2 = fmaf(px, v.x, s2);
        p  = ex2f(fmaf(ag2, v.y, -mg)); px = p * v.y; s0 += p; s1 += px; s2 = fmaf(px, v.y, s2);
        p  = ex2f(fmaf(ag2, v.z, -mg)); px = p * v.z; s0 += p; s1 += px; s2 = fmaf(px, v.z, s2);
        p  = ex2f(fmaf(ag2, v.w, -mg)); px = p * v.w; s0 += p; s1 += px; s2 = fmaf(px, v.w, s2);
    }
    #pragma unroll
    for (int o = 1; o < SLICES; o <<= 1) {
        s0 += __shfl_xor_sync(0xffffffffu, s0, o);
        s1 += __shfl_xor_sync(0xffffffffu, s1, o);
        s2 += __shfl_xor_sync(0xffffffffu, s2, o);
    }
    if (sl == 0) {
        const float inv = 1.0f / s0;
        const float mv  = s1 * inv;
        mArr[g] = mv;
        dArr[g] = fmaf(-mv, mv, s2 * inv);   // Var = m'(alpha), exact derivative
    }
    __syncthreads();

    // ---------- Hermite interpolation: m_i = m(alpha_i) ----------
    const float ai = fmaf(A, xi, C);
    float u = (ai - alo) / hstep;
    int g0 = (int)u;
    g0 = max(0, min(g0, GN - 2));
    const float tt = u - (float)g0;

    const float m0 = mArr[g0],     m1 = mArr[g0 + 1];
    const float d0 = dArr[g0] * hstep, d1 = dArr[g0 + 1] * hstep;
    const float t2 = tt * tt;
    const float t3 = t2 * tt;
    float m =  (2.f*t3 - 3.f*t2 + 1.f) * m0
             + (t3 - 2.f*t2 + tt)      * d0
             + (-2.f*t3 + 3.f*t2)      * m1
             + (t3 - t2)               * d1;

    // ---------- block mean of m ----------
    #pragma unroll
    for (int o = 16; o; o >>= 1) m += __shfl_xor_sync(0xffffffffu, m, o);
    if (lane == 0) ssum[wid] = m;
    __syncthreads();

    if (t == 0) {
        float M = 0.f;
        #pragma unroll
        for (int i = 0; i < 8; ++i) M += ssum[i];
        M *= (1.0f / (float)S_LEN);

        float pooled[4];
        #pragma unroll
        for (int e = 0; e < 4; ++e) {
            const float vw0 = v_w[e*4+0], vw1 = v_w[e*4+1], vw2 = v_w[e*4+2], vw3 = v_w[e*4+3];
            const float va = vw0*w0 + vw1*w1 + vw2*w2 + vw3*w3;
            const float vc = vw0*e0 + vw1*e1 + vw2*e2 + vw3*e3 + v_b[e];
            pooled[e] = fmaf(va, M, vc);
        }

        float y = f2_b[0];
        #pragma unroll
        for (int tt8 = 0; tt8 < 8; ++tt8) {
            float hh = f1_b[tt8];
            #pragma unroll
            for (int e = 0; e < 4; ++e) hh = fmaf(f1_w[tt8*4+e], pooled[e], hh);
            hh = fmaxf(hh, 0.f);
            y = fmaf(f2_w[tt8], hh, y);
        }
        out[b] = y;
    }
}

extern "C" void kernel_launch(void* const* d_in, const int* in_sizes, int n_in,
                              void* d_out, int out_size) {
    const float* x     = (const float*)d_in[0];
    const float* emb_w = (const float*)d_in[1];
    const float* emb_b = (const float*)d_in[2];
    const float* q_w   = (const float*)d_in[3];
    const float* q_b   = (const float*)d_in[4];
    const float* k_w   = (const float*)d_in[5];
    const float* k_b   = (const float*)d_in[6];
    const float* v_w   = (const float*)d_in[7];
    const float* v_b   = (const float*)d_in[8];
    const float* f1_w  = (const float*)d_in[9];
    const float* f1_b  = (const float*)d_in[10];
    const float* f2_w  = (const float*)d_in[11];
    const float* f2_b  = (const float*)d_in[12];

    const int B = in_sizes[0] / S_LEN;

    pico_transformer_adder_kernel<<<B, S_LEN>>>(
        x, emb_w, emb_b, q_w, q_b, k_w, k_b, v_w, v_b,
        f1_w, f1_b, f2_w, f2_b, (float*)d_out);
}

// round 3
// speedup vs baseline: 1.7251x; 1.5673x over previous
#include <cuda_runtime.h>

#define S_LEN 256
#define GN 32          // interpolation grid nodes
#define SLICES 8       // threads cooperating per node (GN*SLICES == S_LEN)
#define XPAD 36        // padded slice stride in floats (144B: 16B-aligned, bank-conflict-free)

__device__ __forceinline__ float ex2f(float v) {
    float y;
    asm("ex2.approx.ftz.f32 %0, %1;" : "=f"(y) : "f"(v));
    return y;
}

__global__ void __launch_bounds__(S_LEN)
pico_transformer_adder_kernel(
    const float* __restrict__ x,
    const float* __restrict__ emb_w,
    const float* __restrict__ emb_b,
    const float* __restrict__ q_w,
    const float* __restrict__ q_b,
    const float* __restrict__ k_w,
    const float* __restrict__ k_b,
    const float* __restrict__ v_w,
    const float* __restrict__ v_b,
    const float* __restrict__ f1_w,
    const float* __restrict__ f1_b,
    const float* __restrict__ f2_w,
    const float* __restrict__ f2_b,
    float* __restrict__ out)
{
    __shared__ __align__(16) float xsp[SLICES * XPAD];   // padded: slice s at xsp[s*36 .. +31]
    __shared__ float smx[8], smn[8], ssum[8];
    __shared__ float mArr[GN], dArr[GN];

    const int b    = blockIdx.x;
    const int t    = threadIdx.x;
    const int lane = t & 31;
    const int wid  = t >> 5;

    const float xi = x[b * S_LEN + t];
    xsp[wid * XPAD + lane] = xi;          // row = warp id (0..7), conflict-free write

    // ---------- uniform scalar constants: alpha_i = A*x_i + C ----------
    const float w0 = emb_w[0], w1 = emb_w[1], w2 = emb_w[2], w3 = emb_w[3];
    const float e0 = emb_b[0], e1 = emb_b[1], e2 = emb_b[2], e3 = emb_b[3];

    float A = 0.f, C = 0.f;
    #pragma unroll
    for (int e = 0; e < 4; ++e) {
        const float qw0 = q_w[e*4+0], qw1 = q_w[e*4+1], qw2 = q_w[e*4+2], qw3 = q_w[e*4+3];
        const float kw0 = k_w[e*4+0], kw1 = k_w[e*4+1], kw2 = k_w[e*4+2], kw3 = k_w[e*4+3];
        const float qa = qw0*w0 + qw1*w1 + qw2*w2 + qw3*w3;
        const float qc = qw0*e0 + qw1*e1 + qw2*e2 + qw3*e3 + q_b[e];
        const float ka = kw0*w0 + kw1*w1 + kw2*w2 + kw3*w3;
        A = fmaf(qa, ka, A);
        C = fmaf(qc, ka, C);
    }
    A *= 0.5f;   // 1/sqrt(d), d=4
    C *= 0.5f;

    // ---------- block min/max of x ----------
    float mx = xi, mn = xi;
    #pragma unroll
    for (int o = 16; o; o >>= 1) {
        mx = fmaxf(mx, __shfl_xor_sync(0xffffffffu, mx, o));
        mn = fminf(mn, __shfl_xor_sync(0xffffffffu, mn, o));
    }
    if (lane == 0) { smx[wid] = mx; smn[wid] = mn; }
    __syncthreads();                      // also publishes xsp[]
    mx = smx[0]; mn = smn[0];
    #pragma unroll
    for (int i = 1; i < 8; ++i) { mx = fmaxf(mx, smx[i]); mn = fminf(mn, smn[i]); }

    // ---------- alpha range and grid ----------
    const float LOG2E = 1.4426950408889634f;
    const float alo = (A >= 0.f) ? fmaf(A, mn, C) : fmaf(A, mx, C);
    const float ahi = (A >= 0.f) ? fmaf(A, mx, C) : fmaf(A, mn, C);
    const float hstep = fmaxf((ahi - alo) * (1.0f / (float)(GN - 1)), 1e-30f);

    // ---------- grid phase: tilted sums at node g over a 32-element slice ----------
    const int g  = t >> 3;      // node 0..31
    const int sl = t & 7;       // slice 0..7 (xor 1,2,4 stays intra-warp)

    const float ag  = fmaf((float)g, hstep, alo);
    const float ag2 = ag * LOG2E;
    const float mg  = fmaxf(ag2 * mx, ag2 * mn);   // max_j ag2*x_j (achieved by data)

    float s0 = 0.f, s1 = 0.f, s2 = 0.f;
    const float4* x4 = (const float4*)(xsp + sl * XPAD);
    #pragma unroll
    for (int j = 0; j < 8; ++j) {
        const float4 v = x4[j];
        float p, px;
        p  = ex2f(fmaf(ag2, v.x, -mg)); px = p * v.x; s0 += p; s1 += px; s2 = fmaf(px, v.x, s2);
        p  = ex2f(fmaf(ag2, v.y, -mg)); px = p * v.y; s0 += p; s1 += px; s2 = fmaf(px, v.y, s2);
        p  = ex2f(fmaf(ag2, v.z, -mg)); px = p * v.z; s0 += p; s1 += px; s2 = fmaf(px, v.z, s2);
        p  = ex2f(fmaf(ag2, v.w, -mg)); px = p * v.w; s0 += p; s1 += px; s2 = fmaf(px, v.w, s2);
    }
    #pragma unroll
    for (int o = 1; o < SLICES; o <<= 1) {
        s0 += __shfl_xor_sync(0xffffffffu, s0, o);
        s1 += __shfl_xor_sync(0xffffffffu, s1, o);
        s2 += __shfl_xor_sync(0xffffffffu, s2, o);
    }
    if (sl == 0) {
        const float inv = __fdividef(1.0f, s0);
        const float mv  = s1 * inv;
        mArr[g] = mv;
        dArr[g] = fmaf(-mv, mv, s2 * inv);   // Var = m'(alpha), exact derivative
    }
    __syncthreads();

    // ---------- Hermite interpolation: m_i = m(alpha_i) ----------
    const float ai = fmaf(A, xi, C);
    float u = __fdividef(ai - alo, hstep);
    int g0 = (int)u;
    g0 = max(0, min(g0, GN - 2));
    const float tt = u - (float)g0;

    const float m0 = mArr[g0],         m1 = mArr[g0 + 1];
    const float d0 = dArr[g0] * hstep, d1 = dArr[g0 + 1] * hstep;
    const float t2 = tt * tt;
    const float t3 = t2 * tt;
    float m =  (2.f*t3 - 3.f*t2 + 1.f) * m0
             + (t3 - 2.f*t2 + tt)      * d0
             + (-2.f*t3 + 3.f*t2)      * m1
             + (t3 - t2)               * d1;

    // ---------- block mean of m ----------
    #pragma unroll
    for (int o = 16; o; o >>= 1) m += __shfl_xor_sync(0xffffffffu, m, o);
    if (lane == 0) ssum[wid] = m;
    __syncthreads();

    if (t == 0) {
        float M = 0.f;
        #pragma unroll
        for (int i = 0; i < 8; ++i) M += ssum[i];
        M *= (1.0f / (float)S_LEN);

        float pooled[4];
        #pragma unroll
        for (int e = 0; e < 4; ++e) {
            const float vw0 = v_w[e*4+0], vw1 = v_w[e*4+1], vw2 = v_w[e*4+2], vw3 = v_w[e*4+3];
            const float va = vw0*w0 + vw1*w1 + vw2*w2 + vw3*w3;
            const float vc = vw0*e0 + vw1*e1 + vw2*e2 + vw3*e3 + v_b[e];
            pooled[e] = fmaf(va, M, vc);
        }

        float y = f2_b[0];
        #pragma unroll
        for (int tt8 = 0; tt8 < 8; ++tt8) {
            float hh = f1_b[tt8];
            #pragma unroll
            for (int e = 0; e < 4; ++e) hh = fmaf(f1_w[tt8*4+e], pooled[e], hh);
            hh = fmaxf(hh, 0.f);
            y = fmaf(f2_w[tt8], hh, y);
        }
        out[b] = y;
    }
}

extern "C" void kernel_launch(void* const* d_in, const int* in_sizes, int n_in,
                              void* d_out, int out_size) {
    const float* x     = (const float*)d_in[0];
    const float* emb_w = (const float*)d_in[1];
    const float* emb_b = (const float*)d_in[2];
    const float* q_w   = (const float*)d_in[3];
    const float* q_b   = (const float*)d_in[4];
    const float* k_w   = (const float*)d_in[5];
    const float* k_b   = (const float*)d_in[6];
    const float* v_w   = (const float*)d_in[7];
    const float* v_b   = (const float*)d_in[8];
    const float* f1_w  = (const float*)d_in[9];
    const float* f1_b  = (const float*)d_in[10];
    const float* f2_w  = (const float*)d_in[11];
    const float* f2_b  = (const float*)d_in[12];

    const int B = in_sizes[0] / S_LEN;

    pico_transformer_adder_kernel<<<B, S_LEN>>>(
        x, emb_w, emb_b, q_w, q_b, k_w, k_b, v_w, v_b,
        f1_w, f1_b, f2_w, f2_b, (float*)d_out);
}

// round 4
// speedup vs baseline: 2.1691x; 1.2574x over previous
#include <cuda_runtime.h>

#define S_LEN 256
#define GN 16          // interpolation grid nodes
#define SLICES 16      // threads per node (GN*SLICES == S_LEN)
#define XSTRIDE 20     // padded slice stride in floats (80B, 16B-aligned)

__device__ __forceinline__ float ex2f(float v) {
    float y;
    asm("ex2.approx.ftz.f32 %0, %1;" : "=f"(y) : "f"(v));
    return y;
}

__global__ void __launch_bounds__(S_LEN)
pico_transformer_adder_kernel(
    const float* __restrict__ x,
    const float* __restrict__ emb_w,
    const float* __restrict__ emb_b,
    const float* __restrict__ q_w,
    const float* __restrict__ q_b,
    const float* __restrict__ k_w,
    const float* __restrict__ k_b,
    const float* __restrict__ v_w,
    const float* __restrict__ v_b,
    const float* __restrict__ f1_w,
    const float* __restrict__ f1_b,
    const float* __restrict__ f2_w,
    const float* __restrict__ f2_b,
    float* __restrict__ out)
{
    __shared__ __align__(16) float xsp[SLICES * XSTRIDE];
    __shared__ float smx[8], smn[8], ssum[8];
    __shared__ float mArr[GN], dArr[GN];
    // uniform constants computed by warp 0 only:
    __shared__ float cA, cC, cF2B;
    __shared__ float cP[8], cR[8], cF[8];

    const int b    = blockIdx.x;
    const int t    = threadIdx.x;
    const int lane = t & 31;
    const int wid  = t >> 5;

    const float xi = x[b * S_LEN + t];
    {   // slice-major padded store: slice s = t/16 holds elems [s*16, s*16+16)
        const int s = t >> 4;
        xsp[s * XSTRIDE + (t & 15)] = xi;
    }

    // ---------- block min/max of x (all warps) ----------
    float mx = xi, mn = xi;
    #pragma unroll
    for (int o = 16; o; o >>= 1) {
        mx = fmaxf(mx, __shfl_xor_sync(0xffffffffu, mx, o));
        mn = fminf(mn, __shfl_xor_sync(0xffffffffu, mn, o));
    }
    if (lane == 0) { smx[wid] = mx; smn[wid] = mn; }

    // ---------- warp 0 only: all grid-uniform scalars ----------
    if (wid == 0) {
        const float w0 = emb_w[0], w1 = emb_w[1], w2 = emb_w[2], w3 = emb_w[3];
        const float e0 = emb_b[0], e1 = emb_b[1], e2 = emb_b[2], e3 = emb_b[3];

        float A = 0.f, C = 0.f;
        float va[4], vc[4];
        #pragma unroll
        for (int e = 0; e < 4; ++e) {
            const float qw0 = q_w[e*4+0], qw1 = q_w[e*4+1], qw2 = q_w[e*4+2], qw3 = q_w[e*4+3];
            const float kw0 = k_w[e*4+0], kw1 = k_w[e*4+1], kw2 = k_w[e*4+2], kw3 = k_w[e*4+3];
            const float vw0 = v_w[e*4+0], vw1 = v_w[e*4+1], vw2 = v_w[e*4+2], vw3 = v_w[e*4+3];
            const float qa = qw0*w0 + qw1*w1 + qw2*w2 + qw3*w3;
            const float qc = qw0*e0 + qw1*e1 + qw2*e2 + qw3*e3 + q_b[e];
            const float ka = kw0*w0 + kw1*w1 + kw2*w2 + kw3*w3;
            A = fmaf(qa, ka, A);
            C = fmaf(qc, ka, C);
            va[e] = vw0*w0 + vw1*w1 + vw2*w2 + vw3*w3;
            vc[e] = vw0*e0 + vw1*e1 + vw2*e2 + vw3*e3 + v_b[e];
        }
        A *= 0.5f;   // 1/sqrt(d), d=4
        C *= 0.5f;

        if (lane < 8) {
            // folded MLP row `lane`: hid = relu(P*M + R), y = f2b + sum F*hid
            float P = 0.f, R = f1_b[lane];
            #pragma unroll
            for (int e = 0; e < 4; ++e) {
                const float fw = f1_w[lane*4+e];
                P = fmaf(fw, va[e], P);
                R = fmaf(fw, vc[e], R);
            }
            cP[lane] = P;
            cR[lane] = R;
            cF[lane] = f2_w[lane];
        }
        if (lane == 0) { cA = A; cC = C; cF2B = f2_b[0]; }
    }
    __syncthreads();   // publishes xsp, smx/smn, and all uniform constants

    mx = smx[0]; mn = smn[0];
    #pragma unroll
    for (int i = 1; i < 8; ++i) { mx = fmaxf(mx, smx[i]); mn = fminf(mn, smn[i]); }

    const float A = cA, C = cC;

    // ---------- alpha range and grid ----------
    const float LOG2E = 1.4426950408889634f;
    const float alo = (A >= 0.f) ? fmaf(A, mn, C) : fmaf(A, mx, C);
    const float ahi = (A >= 0.f) ? fmaf(A, mx, C) : fmaf(A, mn, C);
    const float hstep = fmaxf((ahi - alo) * (1.0f / (float)(GN - 1)), 1e-30f);

    // ---------- grid phase: tilted sums at node g over a 16-element slice ----------
    const int g  = t >> 4;      // node 0..15 (2 nodes per warp)
    const int sl = t & 15;      // slice 0..15 (xor 1,2,4,8 stays intra-group)

    const float ag  = fmaf((float)g, hstep, alo);
    const float ag2 = ag * LOG2E;
    const float mg  = fmaxf(ag2 * mx, ag2 * mn);   // max_j ag2*x_j

    float s0 = 0.f, s1 = 0.f, s2 = 0.f;
    const float4* x4 = (const float4*)(xsp + sl * XSTRIDE);
    #pragma unroll
    for (int j = 0; j < 4; ++j) {
        const float4 v = x4[j];
        float p, px;
        p  = ex2f(fmaf(ag2, v.x, -mg)); px = p * v.x; s0 += p; s1 += px; s2 = fmaf(px, v.x, s2);
        p  = ex2f(fmaf(ag2, v.y, -mg)); px = p * v.y; s0 += p; s1 += px; s2 = fmaf(px, v.y, s2);
        p  = ex2f(fmaf(ag2, v.z, -mg)); px = p * v.z; s0 += p; s1 += px; s2 = fmaf(px, v.z, s2);
        p  = ex2f(fmaf(ag2, v.w, -mg)); px = p * v.w; s0 += p; s1 += px; s2 = fmaf(px, v.w, s2);
    }
    #pragma unroll
    for (int o = 1; o < SLICES; o <<= 1) {
        s0 += __shfl_xor_sync(0xffffffffu, s0, o);
        s1 += __shfl_xor_sync(0xffffffffu, s1, o);
        s2 += __shfl_xor_sync(0xffffffffu, s2, o);
    }
    if (sl == 0) {
        const float inv = __fdividef(1.0f, s0);
        const float mv  = s1 * inv;
        mArr[g] = mv;
        dArr[g] = fmaf(-mv, mv, s2 * inv);   // Var = m'(alpha)
    }
    __syncthreads();

    // ---------- Hermite interpolation: m_i = m(alpha_i) ----------
    const float ai = fmaf(A, xi, C);
    const float u  = __fdividef(ai - alo, hstep);
    int g0 = (int)u;
    g0 = max(0, min(g0, GN - 2));
    const float tt = u - (float)g0;

    const float m0 = mArr[g0],         m1 = mArr[g0 + 1];
    const float d0 = dArr[g0] * hstep, d1 = dArr[g0 + 1] * hstep;
    const float t2 = tt * tt;
    const float t3 = t2 * tt;
    float m =  (2.f*t3 - 3.f*t2 + 1.f) * m0
             + (t3 - 2.f*t2 + tt)      * d0
             + (-2.f*t3 + 3.f*t2)      * m1
             + (t3 - t2)               * d1;

    // ---------- block mean of m ----------
    #pragma unroll
    for (int o = 16; o; o >>= 1) m += __shfl_xor_sync(0xffffffffu, m, o);
    if (lane == 0) ssum[wid] = m;
    __syncthreads();

    if (t == 0) {
        float M = 0.f;
        #pragma unroll
        for (int i = 0; i < 8; ++i) M += ssum[i];
        M *= (1.0f / (float)S_LEN);

        float y = cF2B;
        #pragma unroll
        for (int i = 0; i < 8; ++i)
            y = fmaf(cF[i], fmaxf(fmaf(cP[i], M, cR[i]), 0.f), y);
        out[b] = y;
    }
}

extern "C" void kernel_launch(void* const* d_in, const int* in_sizes, int n_in,
                              void* d_out, int out_size) {
    const float* x     = (const float*)d_in[0];
    const float* emb_w = (const float*)d_in[1];
    const float* emb_b = (const float*)d_in[2];
    const float* q_w   = (const float*)d_in[3];
    const float* q_b   = (const float*)d_in[4];
    const float* k_w   = (const float*)d_in[5];
    const float* k_b   = (const float*)d_in[6];
    const float* v_w   = (const float*)d_in[7];
    const float* v_b   = (const float*)d_in[8];
    const float* f1_w  = (const float*)d_in[9];
    const float* f1_b  = (const float*)d_in[10];
    const float* f2_w  = (const float*)d_in[11];
    const float* f2_b  = (const float*)d_in[12];

    const int B = in_sizes[0] / S_LEN;

    pico_transformer_adder_kernel<<<B, S_LEN>>>(
        x, emb_w, emb_b, q_w, q_b, k_w, k_b, v_w, v_b,
        f1_w, f1_b, f2_w, f2_b, (float*)d_out);
}

// round 5
// speedup vs baseline: 2.1771x; 1.0037x over previous
#include <cuda_runtime.h>

#define S_LEN 256
#define GN 16          // interpolation grid nodes
#define SLICES 16      // threads per node (GN*SLICES == S_LEN)
#define XSTRIDE 20     // padded slice stride in floats (80B, 16B-aligned)

__device__ __forceinline__ float ex2f(float v) {
    float y;
    asm("ex2.approx.ftz.f32 %0, %1;" : "=f"(y) : "f"(v));
    return y;
}

__global__ void __launch_bounds__(S_LEN)
pico_transformer_adder_kernel(
    const float* __restrict__ x,
    const float* __restrict__ emb_w,
    const float* __restrict__ emb_b,
    const float* __restrict__ q_w,
    const float* __restrict__ q_b,
    const float* __restrict__ k_w,
    const float* __restrict__ k_b,
    const float* __restrict__ v_w,
    const float* __restrict__ v_b,
    const float* __restrict__ f1_w,
    const float* __restrict__ f1_b,
    const float* __restrict__ f2_w,
    const float* __restrict__ f2_b,
    float* __restrict__ out,
    int Btot)
{
    __shared__ __align__(16) float xsp[2][SLICES * XSTRIDE];
    __shared__ float smx[2][8], smn[2][8], ssum[2][8];
    __shared__ float mArr[2][GN], dArr[2][GN];
    __shared__ float cA, cC, cF2B;
    __shared__ float cP[8], cR[8], cF[8];

    const int t    = threadIdx.x;
    const int lane = t & 31;
    const int wid  = t >> 5;

    const int b0 = 2 * blockIdx.x;
    const int b1 = min(b0 + 1, Btot - 1);

    const float xi0 = x[b0 * S_LEN + t];
    const float xi1 = x[b1 * S_LEN + t];
    {
        const int s = t >> 4, c = t & 15;
        xsp[0][s * XSTRIDE + c] = xi0;
        xsp[1][s * XSTRIDE + c] = xi1;
    }

    // ---------- block min/max per batch (interleaved, ILP 4) ----------
    float mx0 = xi0, mn0 = xi0, mx1 = xi1, mn1 = xi1;
    #pragma unroll
    for (int o = 16; o; o >>= 1) {
        mx0 = fmaxf(mx0, __shfl_xor_sync(0xffffffffu, mx0, o));
        mn0 = fminf(mn0, __shfl_xor_sync(0xffffffffu, mn0, o));
        mx1 = fmaxf(mx1, __shfl_xor_sync(0xffffffffu, mx1, o));
        mn1 = fminf(mn1, __shfl_xor_sync(0xffffffffu, mn1, o));
    }
    if (lane == 0) {
        smx[0][wid] = mx0; smn[0][wid] = mn0;
        smx[1][wid] = mx1; smn[1][wid] = mn1;
    }

    // ---------- warp 0 only: grid-uniform scalars ----------
    if (wid == 0) {
        const float w0 = emb_w[0], w1 = emb_w[1], w2 = emb_w[2], w3 = emb_w[3];
        const float e0 = emb_b[0], e1 = emb_b[1], e2 = emb_b[2], e3 = emb_b[3];

        float A = 0.f, C = 0.f;
        float va[4], vc[4];
        #pragma unroll
        for (int e = 0; e < 4; ++e) {
            const float qw0 = q_w[e*4+0], qw1 = q_w[e*4+1], qw2 = q_w[e*4+2], qw3 = q_w[e*4+3];
            const float kw0 = k_w[e*4+0], kw1 = k_w[e*4+1], kw2 = k_w[e*4+2], kw3 = k_w[e*4+3];
            const float vw0 = v_w[e*4+0], vw1 = v_w[e*4+1], vw2 = v_w[e*4+2], vw3 = v_w[e*4+3];
            const float qa = qw0*w0 + qw1*w1 + qw2*w2 + qw3*w3;
            const float qc = qw0*e0 + qw1*e1 + qw2*e2 + qw3*e3 + q_b[e];
            const float ka = kw0*w0 + kw1*w1 + kw2*w2 + kw3*w3;
            A = fmaf(qa, ka, A);
            C = fmaf(qc, ka, C);
            va[e] = vw0*w0 + vw1*w1 + vw2*w2 + vw3*w3;
            vc[e] = vw0*e0 + vw1*e1 + vw2*e2 + vw3*e3 + v_b[e];
        }
        A *= 0.5f;   // 1/sqrt(d), d=4
        C *= 0.5f;

        if (lane < 8) {
            float P = 0.f, R = f1_b[lane];
            #pragma unroll
            for (int e = 0; e < 4; ++e) {
                const float fw = f1_w[lane*4+e];
                P = fmaf(fw, va[e], P);
                R = fmaf(fw, vc[e], R);
            }
            cP[lane] = P;
            cR[lane] = R;
            cF[lane] = f2_w[lane];
        }
        if (lane == 0) { cA = A; cC = C; cF2B = f2_b[0]; }
    }
    __syncthreads();   // publishes xsp, smx/smn, uniforms

    mx0 = smx[0][0]; mn0 = smn[0][0]; mx1 = smx[1][0]; mn1 = smn[1][0];
    #pragma unroll
    for (int i = 1; i < 8; ++i) {
        mx0 = fmaxf(mx0, smx[0][i]); mn0 = fminf(mn0, smn[0][i]);
        mx1 = fmaxf(mx1, smx[1][i]); mn1 = fminf(mn1, smn[1][i]);
    }

    const float A = cA, C = cC;
    const float LOG2E = 1.4426950408889634f;

    const float alo0 = (A >= 0.f) ? fmaf(A, mn0, C) : fmaf(A, mx0, C);
    const float ahi0 = (A >= 0.f) ? fmaf(A, mx0, C) : fmaf(A, mn0, C);
    const float alo1 = (A >= 0.f) ? fmaf(A, mn1, C) : fmaf(A, mx1, C);
    const float ahi1 = (A >= 0.f) ? fmaf(A, mx1, C) : fmaf(A, mn1, C);
    const float h0 = fmaxf((ahi0 - alo0) * (1.0f / (float)(GN - 1)), 1e-30f);
    const float h1 = fmaxf((ahi1 - alo1) * (1.0f / (float)(GN - 1)), 1e-30f);

    // ---------- grid phase: node g, slice sl, both batches (ILP 2) ----------
    const int g  = t >> 4;
    const int sl = t & 15;

    const float ag20 = fmaf((float)g, h0, alo0) * LOG2E;
    const float ag21 = fmaf((float)g, h1, alo1) * LOG2E;
    const float mg0  = fmaxf(ag20 * mx0, ag20 * mn0);
    const float mg1  = fmaxf(ag21 * mx1, ag21 * mn1);

    float s00 = 0.f, s01 = 0.f, s02 = 0.f;
    float s10 = 0.f, s11 = 0.f, s12 = 0.f;
    const float4* xa = (const float4*)(xsp[0] + sl * XSTRIDE);
    const float4* xb = (const float4*)(xsp[1] + sl * XSTRIDE);
    #pragma unroll
    for (int j = 0; j < 4; ++j) {
        const float4 va_ = xa[j];
        const float4 vb_ = xb[j];
        float p, px;
        p = ex2f(fmaf(ag20, va_.x, -mg0)); px = p*va_.x; s00 += p; s01 += px; s02 = fmaf(px, va_.x, s02);
        p = ex2f(fmaf(ag21, vb_.x, -mg1)); px = p*vb_.x; s10 += p; s11 += px; s12 = fmaf(px, vb_.x, s12);
        p = ex2f(fmaf(ag20, va_.y, -mg0)); px = p*va_.y; s00 += p; s01 += px; s02 = fmaf(px, va_.y, s02);
        p = ex2f(fmaf(ag21, vb_.y, -mg1)); px = p*vb_.y; s10 += p; s11 += px; s12 = fmaf(px, vb_.y, s12);
        p = ex2f(fmaf(ag20, va_.z, -mg0)); px = p*va_.z; s00 += p; s01 += px; s02 = fmaf(px, va_.z, s02);
        p = ex2f(fmaf(ag21, vb_.z, -mg1)); px = p*vb_.z; s10 += p; s11 += px; s12 = fmaf(px, vb_.z, s12);
        p = ex2f(fmaf(ag20, va_.w, -mg0)); px = p*va_.w; s00 += p; s01 += px; s02 = fmaf(px, va_.w, s02);
        p = ex2f(fmaf(ag21, vb_.w, -mg1)); px = p*vb_.w; s10 += p; s11 += px; s12 = fmaf(px, vb_.w, s12);
    }
    #pragma unroll
    for (int o = 1; o < SLICES; o <<= 1) {
        s00 += __shfl_xor_sync(0xffffffffu, s00, o);
        s01 += __shfl_xor_sync(0xffffffffu, s01, o);
        s02 += __shfl_xor_sync(0xffffffffu, s02, o);
        s10 += __shfl_xor_sync(0xffffffffu, s10, o);
        s11 += __shfl_xor_sync(0xffffffffu, s11, o);
        s12 += __shfl_xor_sync(0xffffffffu, s12, o);
    }
    if (sl == 0) {
        const float inv0 = __fdividef(1.0f, s00);
        const float inv1 = __fdividef(1.0f, s10);
        const float mv0  = s01 * inv0;
        const float mv1  = s11 * inv1;
        mArr[0][g] = mv0;
        mArr[1][g] = mv1;
        dArr[0][g] = fmaf(-mv0, mv0, s02 * inv0);
        dArr[1][g] = fmaf(-mv1, mv1, s12 * inv1);
    }
    __syncthreads();

    // ---------- Hermite interpolation for both batches ----------
    float m0r, m1r;
    {
        const float ai = fmaf(A, xi0, C);
        const float u  = __fdividef(ai - alo0, h0);
        int g0 = max(0, min((int)u, GN - 2));
        const float tt = u - (float)g0;
        const float ma = mArr[0][g0],      mb = mArr[0][g0+1];
        const float da = dArr[0][g0] * h0, db = dArr[0][g0+1] * h0;
        const float t2 = tt*tt, t3 = t2*tt;
        m0r = (2.f*t3-3.f*t2+1.f)*ma + (t3-2.f*t2+tt)*da + (-2.f*t3+3.f*t2)*mb + (t3-t2)*db;
    }
    {
        const float ai = fmaf(A, xi1, C);
        const float u  = __fdividef(ai - alo1, h1);
        int g0 = max(0, min((int)u, GN - 2));
        const float tt = u - (float)g0;
        const float ma = mArr[1][g0],      mb = mArr[1][g0+1];
        const float da = dArr[1][g0] * h1, db = dArr[1][g0+1] * h1;
        const float t2 = tt*tt, t3 = t2*tt;
        m1r = (2.f*t3-3.f*t2+1.f)*ma + (t3-2.f*t2+tt)*da + (-2.f*t3+3.f*t2)*mb + (t3-t2)*db;
    }

    // ---------- block means ----------
    #pragma unroll
    for (int o = 16; o; o >>= 1) {
        m0r += __shfl_xor_sync(0xffffffffu, m0r, o);
        m1r += __shfl_xor_sync(0xffffffffu, m1r, o);
    }
    if (lane == 0) { ssum[0][wid] = m0r; ssum[1][wid] = m1r; }
    __syncthreads();

    if (t == 0) {
        float M0 = 0.f, M1 = 0.f;
        #pragma unroll
        for (int i = 0; i < 8; ++i) { M0 += ssum[0][i]; M1 += ssum[1][i]; }
        M0 *= (1.0f / (float)S_LEN);
        M1 *= (1.0f / (float)S_LEN);

        float y0 = cF2B, y1 = cF2B;
        #pragma unroll
        for (int i = 0; i < 8; ++i) {
            const float P = cP[i], R = cR[i], F = cF[i];
            y0 = fmaf(F, fmaxf(fmaf(P, M0, R), 0.f), y0);
            y1 = fmaf(F, fmaxf(fmaf(P, M1, R), 0.f), y1);
        }
        out[b0] = y0;
        out[b1] = y1;   // if b1==b0 (odd B), same value rewritten: deterministic
    }
}

extern "C" void kernel_launch(void* const* d_in, const int* in_sizes, int n_in,
                              void* d_out, int out_size) {
    const float* x     = (const float*)d_in[0];
    const float* emb_w = (const float*)d_in[1];
    const float* emb_b = (const float*)d_in[2];
    const float* q_w   = (const float*)d_in[3];
    const float* q_b   = (const float*)d_in[4];
    const float* k_w   = (const float*)d_in[5];
    const float* k_b   = (const float*)d_in[6];
    const float* v_w   = (const float*)d_in[7];
    const float* v_b   = (const float*)d_in[8];
    const float* f1_w  = (const float*)d_in[9];
    const float* f1_b  = (const float*)d_in[10];
    const float* f2_w  = (const float*)d_in[11];
    const float* f2_b  = (const float*)d_in[12];

    const int B = in_sizes[0] / S_LEN;
    const int blocks = (B + 1) / 2;

    pico_transformer_adder_kernel<<<blocks, S_LEN>>>(
        x, emb_w, emb_b, q_w, q_b, k_w, k_b, v_w, v_b,
        f1_w, f1_b, f2_w, f2_b, (float*)d_out, B);
}